// round 13
// baseline (speedup 1.0000x reference)
#include <cuda_runtime.h>
#include <cuda_fp16.h>
#include <math.h>
#include <stdint.h>

#define NB 8
#define CC 256
#define HH 64
#define WW 64
#define LL 4096
#define MTOT 32768
#define OMC 216

typedef unsigned short u16;

__device__ float g_om  [(size_t)MTOT * 256];   // offsets+masks, pitch 256
__device__ u16 g_valh[(size_t)MTOT * CC];      // value proj (m,c) fp16 (sampler input)
__device__ u16 g_xh[(size_t)MTOT * CC];        // x  (m,k) fp16
__device__ u16 g_dh[(size_t)MTOT * CC];        // dwconv (m,k) fp16
__device__ u16 g_sh[(size_t)MTOT * CC];        // sampled (m,k) fp16
__device__ u16 g_bh[3 * 65536];                // weights (j,k) fp16

// ---- helpers ----
__device__ __forceinline__ uint32_t smem_u32(const void* p) {
    uint32_t a;
    asm("{ .reg .u64 t; cvta.to.shared.u64 t, %1; cvt.u32.u64 %0, t; }" : "=r"(a) : "l"(p));
    return a;
}
#define CPA(sa, ga) asm volatile("cp.async.cg.shared.global [%0], [%1], 16;" :: "r"(sa), "l"(ga))
#define CPC()       asm volatile("cp.async.commit_group;")
#define CPW(n)      asm volatile("cp.async.wait_group %0;" :: "n"(n))

__device__ __forceinline__ void ldx4(uint32_t* r, uint32_t a) {
    asm volatile("ldmatrix.sync.aligned.m8n8.x4.shared.b16 {%0,%1,%2,%3}, [%4];"
                 : "=r"(r[0]), "=r"(r[1]), "=r"(r[2]), "=r"(r[3]) : "r"(a));
}
__device__ __forceinline__ void mma16816(float* d, const uint32_t* a, const uint32_t* b) {
    asm volatile("mma.sync.aligned.m16n8k16.row.col.f32.f16.f16.f32 "
                 "{%0,%1,%2,%3},{%4,%5,%6,%7},{%8,%9},{%0,%1,%2,%3};"
                 : "+f"(d[0]), "+f"(d[1]), "+f"(d[2]), "+f"(d[3])
                 : "r"(a[0]), "r"(a[1]), "r"(a[2]), "r"(a[3]), "r"(b[0]), "r"(b[1]));
}
__device__ __forceinline__ u16 h16(float v) {
    __half hb = __float2half_rn(v);
    return *(u16*)&hb;
}

// ---- weight fp16 round: om_w (pad 256), vp_w, op_w -> g_bh ----
__global__ void wsplit_kernel(const float* __restrict__ om_w, const float* __restrict__ vp_w,
                              const float* __restrict__ op_w)
{
    int idx = blockIdx.x * 256 + threadIdx.x;
    int w = idx >> 16, j = (idx >> 8) & 255, k = idx & 255;
    float v = 0.f;
    if (w == 0)      { if (j < OMC) v = om_w[j * 256 + k]; }
    else if (w == 1) v = vp_w[j * 256 + k];
    else             v = op_w[j * 256 + k];
    g_bh[idx] = h16(v);
}

// ---- fused: depthwise conv + transpose + fp16 (g_dh) AND x transpose + fp16 (g_xh) ----
__global__ void dwsplit_kernel(const float* __restrict__ x, const float* __restrict__ w,
                               const float* __restrict__ b)
{
    __shared__ float t[32][33];   // conv result
    __shared__ float t2[32][33];  // raw x
    int n = blockIdx.z, c0 = blockIdx.y * 32, l0 = blockIdx.x * 32;
    int tx = threadIdx.x, ty = threadIdx.y;
    int l = l0 + tx;
    int yy = l >> 6, xx = l & 63;
#pragma unroll
    for (int i = 0; i < 4; i++) {
        int c = c0 + ty + 8 * i;
        const float* xp = x + ((size_t)n * CC + c) * LL;
        const float* wp = w + c * 9;
        float acc = b[c];
#pragma unroll
        for (int ky = 0; ky < 3; ky++) {
            int y = yy + ky - 1;
            if ((unsigned)y < HH)
#pragma unroll
                for (int kx = 0; kx < 3; kx++) {
                    int xc = xx + kx - 1;
                    if ((unsigned)xc < WW) acc = fmaf(wp[ky * 3 + kx], xp[y * WW + xc], acc);
                }
        }
        t[ty + 8 * i][tx] = acc;
        t2[ty + 8 * i][tx] = xp[l];
    }
    __syncthreads();
    size_t ob = ((size_t)n * LL + l0) * CC + c0;
#pragma unroll
    for (int i = 0; i < 4; i++) {
        size_t o = ob + (size_t)(ty + 8 * i) * CC + tx;
        g_dh[o] = h16(t[tx][ty + 8 * i]);
        g_xh[o] = h16(t2[tx][ty + 8 * i]);
    }
}

// ---- fp16 HMMA GEMM: C[m,j] = sum_k A[m,k]*W[j,k] (+bias) ----
// CTA 128x128, 8 warps (2m x 4n), k-step 32, 3-stage cp.async, 2 CTAs/SM.
#define STG 16384
#define GEMM_SMEM 67584   // epilogue transpose (128*132*4) dominates

__global__ __launch_bounds__(256, 2)
void gemm_mma(int fused, const float* __restrict__ bias_a, const float* __restrict__ bias_b,
              float* __restrict__ outp)
{
    extern __shared__ char smem[];
    uint32_t sb = smem_u32(smem);
    int tid = threadIdx.x, lane = tid & 31, wid = tid >> 5;
    int warpm = wid >> 2, warpn = wid & 3;
    int m0 = blockIdx.x * 128, ntile = blockIdx.y * 128;

    int asel, wsel, Ncols, omode;
    const float* bias;
    if (fused) {
        if (blockIdx.z == 0) { asel = 1; wsel = 0; Ncols = OMC; omode = 1; bias = bias_a; }
        else                 { asel = 0; wsel = 1; Ncols = 256; omode = 0; bias = bias_b; }
    } else                   { asel = 2; wsel = 2; Ncols = 256; omode = 2; bias = nullptr; }

    const u16* Ah = (asel == 0) ? g_xh : ((asel == 1) ? g_dh : g_sh);
    const u16* Bh = g_bh + wsel * 65536;

    int crow = tid >> 1, chalf = tid & 1;
    uint32_t csel = (crow >> 1) & 3;
    uint32_t ssw0 = (((uint32_t)chalf * 2 + 0) ^ csel) * 16;
    uint32_t ssw1 = (((uint32_t)chalf * 2 + 1) ^ csel) * 16;
    const u16* gA0 = Ah + (size_t)(m0 + crow) * 256 + chalf * 16;
    const u16* gB0 = Bh + (size_t)(ntile + crow) * 256 + chalf * 16;

    auto issue = [&](int s, int kc) {
        uint32_t b0 = sb + s * STG + (uint32_t)crow * 64;
        const u16* p;
        p = gA0 + kc * 32; CPA(b0 + ssw0, p);        CPA(b0 + ssw1, p + 8);
        p = gB0 + kc * 32; CPA(b0 + 8192 + ssw0, p); CPA(b0 + 8192 + ssw1, p + 8);
        CPC();
    };

    int rA = warpm * 64 + (lane & 15);
    uint32_t cbA = (uint32_t)(lane >> 4);
    uint32_t selA = ((uint32_t)rA >> 1) & 3;
    int rB = warpn * 32 + ((lane >> 4) << 3) + (lane & 7);
    uint32_t cbB = (uint32_t)((lane >> 3) & 1);
    uint32_t selB = ((uint32_t)rB >> 1) & 3;

    float acc[4][4][4];
#pragma unroll
    for (int a = 0; a < 4; a++)
#pragma unroll
        for (int b = 0; b < 4; b++)
#pragma unroll
            for (int c = 0; c < 4; c++) acc[a][b][c] = 0.f;

    issue(0, 0);
    issue(1, 1);

    for (int kc = 0; kc < 8; kc++) {
        if (kc < 7) CPW(1); else CPW(0);
        __syncthreads();
        int s = kc % 3;
        if (kc + 2 < 8) issue((kc + 2) % 3, kc + 2);
        uint32_t stg = sb + s * STG;
#pragma unroll
        for (int kk = 0; kk < 2; kk++) {
            uint32_t ah[4][4], bh[4][2];
#pragma unroll
            for (int mb = 0; mb < 4; mb++) {
                uint32_t a = stg + (uint32_t)(rA + mb * 16) * 64 + (((kk * 2 + cbA) ^ selA) * 16);
                ldx4(ah[mb], a);
            }
#pragma unroll
            for (int p = 0; p < 2; p++) {
                uint32_t a = stg + 8192 + (uint32_t)(rB + p * 16) * 64 + (((kk * 2 + cbB) ^ selB) * 16);
                uint32_t r[4];
                ldx4(r, a);
                bh[2 * p][0] = r[0]; bh[2 * p][1] = r[1];
                bh[2 * p + 1][0] = r[2]; bh[2 * p + 1][1] = r[3];
            }
#pragma unroll
            for (int mb = 0; mb < 4; mb++)
#pragma unroll
                for (int nb = 0; nb < 4; nb++)
                    mma16816(acc[mb][nb], ah[mb], bh[nb]);
        }
    }
    __syncthreads();

    if (omode == 0) {
        // value projection: write fp16 (sampler input)
#pragma unroll
        for (int mb = 0; mb < 4; mb++) {
            int m = m0 + warpm * 64 + mb * 16 + (lane >> 2);
            u16* cr = g_valh + (size_t)m * 256;
#pragma unroll
            for (int nb = 0; nb < 4; nb++) {
                int j = ntile + warpn * 32 + nb * 8 + (lane & 3) * 2;
                float b0 = bias[j], b1 = bias[j + 1];
                __half2 v0 = __floats2half2_rn(acc[mb][nb][0] + b0, acc[mb][nb][1] + b1);
                __half2 v1 = __floats2half2_rn(acc[mb][nb][2] + b0, acc[mb][nb][3] + b1);
                *(__half2*)(cr + j) = v0;
                *(__half2*)(cr + 2048 + j) = v1;   // row m+8
            }
        }
    } else if (omode == 1) {
#pragma unroll
        for (int mb = 0; mb < 4; mb++) {
            int m = m0 + warpm * 64 + mb * 16 + (lane >> 2);
            float* cr = g_om + (size_t)m * 256;
#pragma unroll
            for (int nb = 0; nb < 4; nb++) {
                int j = ntile + warpn * 32 + nb * 8 + (lane & 3) * 2;
                if (j < Ncols) {
                    float b0 = bias[j], b1 = bias[j + 1];
                    *(float2*)(cr + j) = make_float2(acc[mb][nb][0] + b0, acc[mb][nb][1] + b1);
                    *(float2*)(cr + 2048 + j) = make_float2(acc[mb][nb][2] + b0, acc[mb][nb][3] + b1);
                }
            }
        }
    } else {
        float* ts = (float*)smem;
#pragma unroll
        for (int mb = 0; mb < 4; mb++) {
            int r = warpm * 64 + mb * 16 + (lane >> 2);
#pragma unroll
            for (int nb = 0; nb < 4; nb++) {
                int j = warpn * 32 + nb * 8 + (lane & 3) * 2;
                ts[j * 132 + r]           = acc[mb][nb][0];
                ts[(j + 1) * 132 + r]     = acc[mb][nb][1];
                ts[j * 132 + r + 8]       = acc[mb][nb][2];
                ts[(j + 1) * 132 + r + 8] = acc[mb][nb][3];
            }
        }
        __syncthreads();
        int nimg = m0 >> 12, l0 = m0 & 4095;
        float* Ob = outp + (size_t)nimg * (CC * LL) + l0 + lane * 4;
        int j0 = tid >> 5;
#pragma unroll
        for (int it = 0; it < 16; it++) {
            int j = j0 + it * 8;
            float4 v = *(float4*)(ts + j * 132 + lane * 4);
            *(float4*)(Ob + (size_t)(ntile + j) * LL) = v;
        }
    }
}

// ---- deformable sampling: thread = (nl, g, 8 channels); fp16 value in/out ----
__global__ void sample_kernel()
{
    int t = blockIdx.x * 256 + threadIdx.x;
    int q = t & 3, g = (t >> 2) & 7, nl = t >> 5;
    int l = nl & (LL - 1);
    int yy = l >> 6, xx = l & 63;
    const float* omp = g_om + (size_t)nl * 256 + g * 27;
    const u16* vb = g_valh + (size_t)(nl >> 12) * ((size_t)LL * CC) + g * 32 + q * 8;

    float acc[8];
#pragma unroll
    for (int i = 0; i < 8; i++) acc[i] = 0.f;
#pragma unroll
    for (int k = 0; k < 9; k++) {
        float py = (float)(yy + (k / 3) - 1) + omp[2 * k];
        float px = (float)(xx + (k % 3) - 1) + omp[2 * k + 1];
        float mk = omp[18 + k];
        float y0f = floorf(py), x0f = floorf(px);
        float ty = py - y0f, tx = px - x0f;
        int y0 = (int)y0f, x0 = (int)x0f;
        float s[8];
#pragma unroll
        for (int i = 0; i < 8; i++) s[i] = 0.f;
#pragma unroll
        for (int dy = 0; dy < 2; dy++)
#pragma unroll
            for (int dx = 0; dx < 2; dx++) {
                int yi = y0 + dy, xi = x0 + dx;
                if (yi >= 0 && yi < HH && xi >= 0 && xi < WW) {
                    float wgt = (dy ? ty : 1.f - ty) * (dx ? tx : 1.f - tx);
                    uint4 v = *(const uint4*)(vb + (size_t)(yi * WW + xi) * CC);
                    const __half2* hp = (const __half2*)&v;
#pragma unroll
                    for (int i = 0; i < 4; i++) {
                        float2 f = __half22float2(hp[i]);
                        s[2 * i]     = fmaf(wgt, f.x, s[2 * i]);
                        s[2 * i + 1] = fmaf(wgt, f.y, s[2 * i + 1]);
                    }
                }
            }
#pragma unroll
        for (int i = 0; i < 8; i++) acc[i] = fmaf(mk, s[i], acc[i]);
    }
    size_t ob = (size_t)nl * 256 + g * 32 + q * 8;
    ushort4 h0, h1;
    h0.x = h16(acc[0]); h0.y = h16(acc[1]); h0.z = h16(acc[2]); h0.w = h16(acc[3]);
    h1.x = h16(acc[4]); h1.y = h16(acc[5]); h1.z = h16(acc[6]); h1.w = h16(acc[7]);
    *(ushort4*)(g_sh + ob) = h0;
    *(ushort4*)(g_sh + ob + 4) = h1;
}

// ---------------------------------------------------------------------------
extern "C" void kernel_launch(void* const* d_in, const int* in_sizes, int n_in,
                              void* d_out, int out_size)
{
    const float* x    = (const float*)d_in[0];
    const float* dw_w = (const float*)d_in[1];
    const float* dw_b = (const float*)d_in[2];
    const float* om_w = (const float*)d_in[3];
    const float* om_b = (const float*)d_in[4];
    const float* vp_w = (const float*)d_in[5];
    const float* vp_b = (const float*)d_in[6];
    const float* op_w = (const float*)d_in[7];
    float* out = (float*)d_out;

    cudaFuncSetAttribute(gemm_mma, cudaFuncAttributeMaxDynamicSharedMemorySize, GEMM_SMEM);

    wsplit_kernel<<<768, 256>>>(om_w, vp_w, op_w);
    dwsplit_kernel<<<dim3(128, 8, NB), dim3(32, 8)>>>(x, dw_w, dw_b);  // -> g_dh + g_xh

    // fused om + vp GEMM (z=0: om -> g_om ; z=1: vp -> g_valh fp16)
    gemm_mma<<<dim3(256, 2, 2), 256, GEMM_SMEM>>>(1, om_b, vp_b, nullptr);
    sample_kernel<<<(MTOT * 32) / 256, 256>>>();                        // -> g_sh
    gemm_mma<<<dim3(256, 2, 1), 256, GEMM_SMEM>>>(0, nullptr, nullptr, out);  // -> d_out
}

// round 16
// speedup vs baseline: 1.5519x; 1.5519x over previous
#include <cuda_runtime.h>
#include <cuda_fp16.h>
#include <math.h>
#include <stdint.h>

#define NB 8
#define CC 256
#define HH 64
#define WW 64
#define LL 4096
#define MTOT 32768
#define OMC 216

typedef unsigned short u16;

__device__ float g_om  [(size_t)MTOT * 256];   // offsets+masks, pitch 256
__device__ u16 g_valh[(size_t)MTOT * CC];      // value proj (m,c) fp16 (sampler input)
__device__ u16 g_xh[(size_t)MTOT * CC];        // x  (m,k) fp16
__device__ u16 g_dh[(size_t)MTOT * CC];        // dwconv (m,k) fp16
__device__ u16 g_sh[(size_t)MTOT * CC];        // sampled (m,k) fp16
__device__ u16 g_bh[3 * 65536];                // weights (j,k) fp16

// ---- helpers ----
__device__ __forceinline__ uint32_t smem_u32(const void* p) {
    uint32_t a;
    asm("{ .reg .u64 t; cvta.to.shared.u64 t, %1; cvt.u32.u64 %0, t; }" : "=r"(a) : "l"(p));
    return a;
}
#define CPA(sa, ga) asm volatile("cp.async.cg.shared.global [%0], [%1], 16;" :: "r"(sa), "l"(ga))
#define CPC()       asm volatile("cp.async.commit_group;")
#define CPW(n)      asm volatile("cp.async.wait_group %0;" :: "n"(n))

__device__ __forceinline__ void ldx4(uint32_t* r, uint32_t a) {
    asm volatile("ldmatrix.sync.aligned.m8n8.x4.shared.b16 {%0,%1,%2,%3}, [%4];"
                 : "=r"(r[0]), "=r"(r[1]), "=r"(r[2]), "=r"(r[3]) : "r"(a));
}
__device__ __forceinline__ void mma16816(float* d, const uint32_t* a, const uint32_t* b) {
    asm volatile("mma.sync.aligned.m16n8k16.row.col.f32.f16.f16.f32 "
                 "{%0,%1,%2,%3},{%4,%5,%6,%7},{%8,%9},{%0,%1,%2,%3};"
                 : "+f"(d[0]), "+f"(d[1]), "+f"(d[2]), "+f"(d[3])
                 : "r"(a[0]), "r"(a[1]), "r"(a[2]), "r"(a[3]), "r"(b[0]), "r"(b[1]));
}
__device__ __forceinline__ u16 h16(float v) {
    __half hb = __float2half_rn(v);
    return *(u16*)&hb;
}

// ---- weight fp16 round: om_w (pad 256), vp_w, op_w -> g_bh ----
__global__ void wsplit_kernel(const float* __restrict__ om_w, const float* __restrict__ vp_w,
                              const float* __restrict__ op_w)
{
    int idx = blockIdx.x * 256 + threadIdx.x;
    int w = idx >> 16, j = (idx >> 8) & 255, k = idx & 255;
    float v = 0.f;
    if (w == 0)      { if (j < OMC) v = om_w[j * 256 + k]; }
    else if (w == 1) v = vp_w[j * 256 + k];
    else             v = op_w[j * 256 + k];
    g_bh[idx] = h16(v);
}

// ---- fused: depthwise conv + transpose + fp16 (g_dh) AND x transpose + fp16 (g_xh) ----
__global__ void dwsplit_kernel(const float* __restrict__ x, const float* __restrict__ w,
                               const float* __restrict__ b)
{
    __shared__ float t[32][33];   // conv result
    __shared__ float t2[32][33];  // raw x
    int n = blockIdx.z, c0 = blockIdx.y * 32, l0 = blockIdx.x * 32;
    int tx = threadIdx.x, ty = threadIdx.y;
    int l = l0 + tx;
    int yy = l >> 6, xx = l & 63;
#pragma unroll
    for (int i = 0; i < 4; i++) {
        int c = c0 + ty + 8 * i;
        const float* xp = x + ((size_t)n * CC + c) * LL;
        const float* wp = w + c * 9;
        float acc = b[c];
#pragma unroll
        for (int ky = 0; ky < 3; ky++) {
            int y = yy + ky - 1;
            if ((unsigned)y < HH)
#pragma unroll
                for (int kx = 0; kx < 3; kx++) {
                    int xc = xx + kx - 1;
                    if ((unsigned)xc < WW) acc = fmaf(wp[ky * 3 + kx], xp[y * WW + xc], acc);
                }
        }
        t[ty + 8 * i][tx] = acc;
        t2[ty + 8 * i][tx] = xp[l];
    }
    __syncthreads();
    size_t ob = ((size_t)n * LL + l0) * CC + c0;
#pragma unroll
    for (int i = 0; i < 4; i++) {
        size_t o = ob + (size_t)(ty + 8 * i) * CC + tx;
        g_dh[o] = h16(t[tx][ty + 8 * i]);
        g_xh[o] = h16(t2[tx][ty + 8 * i]);
    }
}

// ---- fp16 HMMA GEMM: C[m,j] = sum_k A[m,k]*W[j,k] (+bias) ----
// CTA 128x128, 8 warps (2m x 4n), k-step 32, 3-stage cp.async, 2 CTAs/SM.
#define STG 16384
#define GEMM_SMEM 67584   // epilogue transpose (128*132*4) dominates

__global__ __launch_bounds__(256, 2)
void gemm_mma(int fused, const float* __restrict__ bias_a, const float* __restrict__ bias_b,
              float* __restrict__ outp)
{
    extern __shared__ char smem[];
    uint32_t sb = smem_u32(smem);
    int tid = threadIdx.x, lane = tid & 31, wid = tid >> 5;
    int warpm = wid >> 2, warpn = wid & 3;
    int m0 = blockIdx.x * 128, ntile = blockIdx.y * 128;

    int asel, wsel, Ncols, omode;
    const float* bias;
    if (fused) {
        if (blockIdx.z == 0) { asel = 1; wsel = 0; Ncols = OMC; omode = 1; bias = bias_a; }
        else                 { asel = 0; wsel = 1; Ncols = 256; omode = 0; bias = bias_b; }
    } else                   { asel = 2; wsel = 2; Ncols = 256; omode = 2; bias = nullptr; }

    const u16* Ah = (asel == 0) ? g_xh : ((asel == 1) ? g_dh : g_sh);
    const u16* Bh = g_bh + wsel * 65536;

    int crow = tid >> 1, chalf = tid & 1;
    uint32_t csel = (crow >> 1) & 3;
    uint32_t ssw0 = (((uint32_t)chalf * 2 + 0) ^ csel) * 16;
    uint32_t ssw1 = (((uint32_t)chalf * 2 + 1) ^ csel) * 16;
    const u16* gA0 = Ah + (size_t)(m0 + crow) * 256 + chalf * 16;
    const u16* gB0 = Bh + (size_t)(ntile + crow) * 256 + chalf * 16;

    auto issue = [&](int s, int kc) {
        uint32_t b0 = sb + s * STG + (uint32_t)crow * 64;
        const u16* p;
        p = gA0 + kc * 32; CPA(b0 + ssw0, p);        CPA(b0 + ssw1, p + 8);
        p = gB0 + kc * 32; CPA(b0 + 8192 + ssw0, p); CPA(b0 + 8192 + ssw1, p + 8);
        CPC();
    };

    int rA = warpm * 64 + (lane & 15);
    uint32_t cbA = (uint32_t)(lane >> 4);
    uint32_t selA = ((uint32_t)rA >> 1) & 3;
    int rB = warpn * 32 + ((lane >> 4) << 3) + (lane & 7);
    uint32_t cbB = (uint32_t)((lane >> 3) & 1);
    uint32_t selB = ((uint32_t)rB >> 1) & 3;

    float acc[4][4][4];
#pragma unroll
    for (int a = 0; a < 4; a++)
#pragma unroll
        for (int b = 0; b < 4; b++)
#pragma unroll
            for (int c = 0; c < 4; c++) acc[a][b][c] = 0.f;

    issue(0, 0);
    issue(1, 1);

    for (int kc = 0; kc < 8; kc++) {
        if (kc < 7) CPW(1); else CPW(0);
        __syncthreads();
        int s = kc % 3;
        if (kc + 2 < 8) issue((kc + 2) % 3, kc + 2);
        uint32_t stg = sb + s * STG;
#pragma unroll
        for (int kk = 0; kk < 2; kk++) {
            uint32_t ah[4][4], bh[4][2];
#pragma unroll
            for (int mb = 0; mb < 4; mb++) {
                uint32_t a = stg + (uint32_t)(rA + mb * 16) * 64 + (((kk * 2 + cbA) ^ selA) * 16);
                ldx4(ah[mb], a);
            }
#pragma unroll
            for (int p = 0; p < 2; p++) {
                uint32_t a = stg + 8192 + (uint32_t)(rB + p * 16) * 64 + (((kk * 2 + cbB) ^ selB) * 16);
                uint32_t r[4];
                ldx4(r, a);
                bh[2 * p][0] = r[0]; bh[2 * p][1] = r[1];
                bh[2 * p + 1][0] = r[2]; bh[2 * p + 1][1] = r[3];
            }
#pragma unroll
            for (int mb = 0; mb < 4; mb++)
#pragma unroll
                for (int nb = 0; nb < 4; nb++)
                    mma16816(acc[mb][nb], ah[mb], bh[nb]);
        }
    }
    __syncthreads();

    if (omode == 0) {
        // value projection: write fp16 (sampler input)
#pragma unroll
        for (int mb = 0; mb < 4; mb++) {
            int m = m0 + warpm * 64 + mb * 16 + (lane >> 2);
            u16* cr = g_valh + (size_t)m * 256;
#pragma unroll
            for (int nb = 0; nb < 4; nb++) {
                int j = ntile + warpn * 32 + nb * 8 + (lane & 3) * 2;
                float b0 = bias[j], b1 = bias[j + 1];
                __half2 v0 = __floats2half2_rn(acc[mb][nb][0] + b0, acc[mb][nb][1] + b1);
                __half2 v1 = __floats2half2_rn(acc[mb][nb][2] + b0, acc[mb][nb][3] + b1);
                *(__half2*)(cr + j) = v0;
                *(__half2*)(cr + 2048 + j) = v1;   // row m+8
            }
        }
    } else if (omode == 1) {
#pragma unroll
        for (int mb = 0; mb < 4; mb++) {
            int m = m0 + warpm * 64 + mb * 16 + (lane >> 2);
            float* cr = g_om + (size_t)m * 256;
#pragma unroll
            for (int nb = 0; nb < 4; nb++) {
                int j = ntile + warpn * 32 + nb * 8 + (lane & 3) * 2;
                if (j < Ncols) {
                    float b0 = bias[j], b1 = bias[j + 1];
                    *(float2*)(cr + j) = make_float2(acc[mb][nb][0] + b0, acc[mb][nb][1] + b1);
                    *(float2*)(cr + 2048 + j) = make_float2(acc[mb][nb][2] + b0, acc[mb][nb][3] + b1);
                }
            }
        }
    } else {
        float* ts = (float*)smem;
#pragma unroll
        for (int mb = 0; mb < 4; mb++) {
            int r = warpm * 64 + mb * 16 + (lane >> 2);
#pragma unroll
            for (int nb = 0; nb < 4; nb++) {
                int j = warpn * 32 + nb * 8 + (lane & 3) * 2;
                ts[j * 132 + r]           = acc[mb][nb][0];
                ts[(j + 1) * 132 + r]     = acc[mb][nb][1];
                ts[j * 132 + r + 8]       = acc[mb][nb][2];
                ts[(j + 1) * 132 + r + 8] = acc[mb][nb][3];
            }
        }
        __syncthreads();
        int nimg = m0 >> 12, l0 = m0 & 4095;
        float* Ob = outp + (size_t)nimg * (CC * LL) + l0 + lane * 4;
        int j0 = tid >> 5;
#pragma unroll
        for (int it = 0; it < 16; it++) {
            int j = j0 + it * 8;
            float4 v = *(float4*)(ts + j * 132 + lane * 4);
            *(float4*)(Ob + (size_t)(ntile + j) * LL) = v;
        }
    }
}

// ---- deformable sampling: thread = (nl, g, 8 channels); mask folded into corner wgts ----
__global__ void sample_kernel()
{
    int t = blockIdx.x * 256 + threadIdx.x;
    int q = t & 3, g = (t >> 2) & 7, nl = t >> 5;
    int l = nl & (LL - 1);
    int yy = l >> 6, xx = l & 63;
    const float* omp = g_om + (size_t)nl * 256 + g * 27;
    const u16* vb = g_valh + (size_t)(nl >> 12) * ((size_t)LL * CC) + g * 32 + q * 8;

    float acc[8];
#pragma unroll
    for (int i = 0; i < 8; i++) acc[i] = 0.f;
#pragma unroll
    for (int k = 0; k < 9; k++) {
        float py = (float)(yy + (k / 3) - 1) + omp[2 * k];
        float px = (float)(xx + (k % 3) - 1) + omp[2 * k + 1];
        float mk = omp[18 + k];
        float y0f = floorf(py), x0f = floorf(px);
        float ty = py - y0f, tx = px - x0f;
        int y0 = (int)y0f, x0 = (int)x0f;
        // fold mask into the 4 bilinear corner weights (saves per-tap s[] pass)
        float wy0 = mk - mk * ty, wy1 = mk * ty;
        float w00 = wy0 - wy0 * tx, w01 = wy0 * tx;
        float w10 = wy1 - wy1 * tx, w11 = wy1 * tx;
        const float cw[2][2] = { { w00, w01 }, { w10, w11 } };
#pragma unroll
        for (int dy = 0; dy < 2; dy++)
#pragma unroll
            for (int dx = 0; dx < 2; dx++) {
                int yi = y0 + dy, xi = x0 + dx;
                if (yi >= 0 && yi < HH && xi >= 0 && xi < WW) {
                    float wgt = cw[dy][dx];
                    uint4 v = *(const uint4*)(vb + (size_t)(yi * WW + xi) * CC);
                    const __half2* hp = (const __half2*)&v;
#pragma unroll
                    for (int i = 0; i < 4; i++) {
                        float2 f = __half22float2(hp[i]);
                        acc[2 * i]     = fmaf(wgt, f.x, acc[2 * i]);
                        acc[2 * i + 1] = fmaf(wgt, f.y, acc[2 * i + 1]);
                    }
                }
            }
    }
    size_t ob = (size_t)nl * 256 + g * 32 + q * 8;
    ushort4 h0, h1;
    h0.x = h16(acc[0]); h0.y = h16(acc[1]); h0.z = h16(acc[2]); h0.w = h16(acc[3]);
    h1.x = h16(acc[4]); h1.y = h16(acc[5]); h1.z = h16(acc[6]); h1.w = h16(acc[7]);
    *(ushort4*)(g_sh + ob) = h0;
    *(ushort4*)(g_sh + ob + 4) = h1;
}

// ---------------------------------------------------------------------------
extern "C" void kernel_launch(void* const* d_in, const int* in_sizes, int n_in,
                              void* d_out, int out_size)
{
    const float* x    = (const float*)d_in[0];
    const float* dw_w = (const float*)d_in[1];
    const float* dw_b = (const float*)d_in[2];
    const float* om_w = (const float*)d_in[3];
    const float* om_b = (const float*)d_in[4];
    const float* vp_w = (const float*)d_in[5];
    const float* vp_b = (const float*)d_in[6];
    const float* op_w = (const float*)d_in[7];
    float* out = (float*)d_out;

    cudaFuncSetAttribute(gemm_mma, cudaFuncAttributeMaxDynamicSharedMemorySize, GEMM_SMEM);

    wsplit_kernel<<<768, 256>>>(om_w, vp_w, op_w);
    dwsplit_kernel<<<dim3(128, 8, NB), dim3(32, 8)>>>(x, dw_w, dw_b);  // -> g_dh + g_xh

    // fused om + vp GEMM (z=0: om -> g_om ; z=1: vp -> g_valh fp16)
    gemm_mma<<<dim3(256, 2, 2), 256, GEMM_SMEM>>>(1, om_b, vp_b, nullptr);
    sample_kernel<<<(MTOT * 32) / 256, 256>>>();                        // -> g_sh
    gemm_mma<<<dim3(256, 2, 1), 256, GEMM_SMEM>>>(0, nullptr, nullptr, out);  // -> d_out
}